// round 15
// baseline (speedup 1.0000x reference)
#include <cuda_runtime.h>
#include <cuda_fp16.h>
#include <cstdint>
#include <cstddef>

// ---------------------------------------------------------------------------
// QDense via quaternion complex-Karatsuba: 12 products of [B,1024]x[1024,1024]
// (75% of the dense MACs; tensor-busy proved = 0.75x dense in R14).
// R14->R15: regs 255 -> <=128 by halving warp tile (16 warps x 32x32), which
//   restores 4 warps/SMSP (occ 25%) and removes spills; same HMMA count.
//   P1=x0W0 P2=x1W1 P3=(x0+x1)(W0+W1)  P4=x2W2 P5=x3W3 P6=(x2+x3)(W2-W3)
//   P7=x0W2 P8=x1W3 P9=(x0+x1)(W2+W3)  P10=x2W0 P11=x3W1 P12=(x2+x3)(W0-W1)
//   out_r=P1-P2-P4-P5            out_i=-P1-P2+P3+P4-P5-P6
//   out_j=P7-P8+P10+P11          out_k=-P7-P8+P9-P10+P11+P12
// ---------------------------------------------------------------------------

#define IN_F   4096
#define OUT_F  4096
#define BATCH  4096
#define QOUT   1024
#define W_ELEMS (1024 * 1024)

#define BM 128
#define BN 128
#define BK 64                          // k half-elements per stage
#define STAGES 3
#define SEGS 6
#define KT_PER_SEG 16                  // 1024 / 64
#define TOT_KT (SEGS * KT_PER_SEG)     // 96
#define THREADS 512

#define ROWB 144                       // padded row stride in bytes
#define A_ST_BYTES (BM * ROWB)         // 18432
#define B_ST_BYTES (BN * ROWB)         // 18432
#define STAGE_BYTES (A_ST_BYTES + B_ST_BYTES)   // 36864
#define SMEM_TOTAL (STAGES * STAGE_BYTES)       // 110592

// Scratch: device globals (the only legal scratch)
__device__ __half g_lh[(size_t)6 * BATCH * 1024];   // L0..L5          (48 MB)
__device__ __half g_wh8[(size_t)8 * 1024 * 1024];   // 8 RHS matrices  (16 MB)
__device__ float  g_bias[OUT_F];

__constant__ int   c_q[4][4] = {{0,1,2,3},{1,0,3,2},{2,3,0,1},{3,2,1,0}};
__constant__ float c_s[4][4] = {{ 1.f,-1.f,-1.f,-1.f},
                                { 1.f, 1.f, 1.f,-1.f},
                                { 1.f,-1.f, 1.f, 1.f},
                                { 1.f, 1.f,-1.f, 1.f}};

// per-segment LHS index, RHS index per pair, fold signs per pair
__constant__ int   c_lidx[6]    = {0, 1, 4, 2, 3, 5};
__constant__ int   c_ridx[2][6] = {{0, 1, 4, 2, 3, 5},   // W0 W1 W0+W1 W2 W3 W2-W3
                                   {2, 3, 6, 0, 1, 7}};  // W2 W3 W2+W3 W0 W1 W0-W1
__constant__ float c_sA[2][6] = {{ 1.f,-1.f, 0.f,-1.f,-1.f, 0.f},   // out_r / out_j
                                 { 1.f,-1.f, 0.f, 1.f, 1.f, 0.f}};
__constant__ float c_sB[2][6] = {{-1.f,-1.f, 1.f, 1.f,-1.f,-1.f},   // out_i / out_k
                                 {-1.f,-1.f, 1.f,-1.f, 1.f, 1.f}};

// ------------------------------- helpers -----------------------------------

__device__ __forceinline__ uint32_t smem_u32(const void* p) {
    uint32_t a;
    asm("{ .reg .u64 t; cvta.to.shared.u64 t, %1; cvt.u32.u64 %0, t; }"
        : "=r"(a) : "l"(p));
    return a;
}

__device__ __forceinline__ void cp16(uint32_t dst, const void* src) {
    asm volatile("cp.async.cg.shared.global [%0], [%1], 16;" :: "r"(dst), "l"(src));
}

__device__ __forceinline__ void cp_commit() {
    asm volatile("cp.async.commit_group;" ::: "memory");
}

template <int N>
__device__ __forceinline__ void cp_wait() {
    asm volatile("cp.async.wait_group %0;" :: "n"(N) : "memory");
}

__device__ __forceinline__ void ldmx4(uint32_t* r, uint32_t addr) {
    asm volatile(
        "ldmatrix.sync.aligned.m8n8.x4.shared.b16 {%0,%1,%2,%3}, [%4];"
        : "=r"(r[0]), "=r"(r[1]), "=r"(r[2]), "=r"(r[3]) : "r"(addr));
}

__device__ __forceinline__ void mma_f16(float* d, const uint32_t* a,
                                        uint32_t b0, uint32_t b1) {
    asm volatile(
        "mma.sync.aligned.m16n8k16.row.col.f32.f16.f16.f32 "
        "{%0,%1,%2,%3}, {%4,%5,%6,%7}, {%8,%9}, {%0,%1,%2,%3};"
        : "+f"(d[0]), "+f"(d[1]), "+f"(d[2]), "+f"(d[3])
        : "r"(a[0]), "r"(a[1]), "r"(a[2]), "r"(a[3]), "r"(b0), "r"(b1));
}

// ------------------------------ prep kernels --------------------------------

// Build L0..L3 (x components) and L4=x0+x1, L5=x2+x3, all fp16.
__global__ void k_lhs(const float* __restrict__ x) {
    int id = blockIdx.x * blockDim.x + threadIdx.x;     // b*256 + i4
    int b  = id >> 8;
    int i4 = id & 255;                                  // float4 within 1024
    const float4* xr = (const float4*)x + (size_t)b * 1024;  // 1024 float4/row
    float4 v[4];
#pragma unroll
    for (int c = 0; c < 4; c++) v[c] = xr[c * 256 + i4];

    __half2* L = (__half2*)g_lh;
    size_t stride2 = (size_t)BATCH * 512;               // half2 per L matrix
    size_t base = (size_t)b * 512 + i4 * 2;             // half2 idx within matrix
#pragma unroll
    for (int c = 0; c < 4; c++) {
        L[c * stride2 + base]     = make_half2(__float2half_rn(v[c].x),
                                               __float2half_rn(v[c].y));
        L[c * stride2 + base + 1] = make_half2(__float2half_rn(v[c].z),
                                               __float2half_rn(v[c].w));
    }
    float4 s01 = make_float4(v[0].x + v[1].x, v[0].y + v[1].y,
                             v[0].z + v[1].z, v[0].w + v[1].w);
    float4 s23 = make_float4(v[2].x + v[3].x, v[2].y + v[3].y,
                             v[2].z + v[3].z, v[2].w + v[3].w);
    L[4 * stride2 + base]     = make_half2(__float2half_rn(s01.x), __float2half_rn(s01.y));
    L[4 * stride2 + base + 1] = make_half2(__float2half_rn(s01.z), __float2half_rn(s01.w));
    L[5 * stride2 + base]     = make_half2(__float2half_rn(s23.x), __float2half_rn(s23.y));
    L[5 * stride2 + base + 1] = make_half2(__float2half_rn(s23.z), __float2half_rn(s23.w));
}

// Build 8 RHS matrices: 0..3 = W0..W3, 4=W0+W1, 5=W2-W3, 6=W2+W3, 7=W0-W1.
__global__ void k_rhs(const float* __restrict__ W0, const float* __restrict__ W1,
                      const float* __restrict__ W2, const float* __restrict__ W3) {
    int id = blockIdx.x * blockDim.x + threadIdx.x;     // o*256 + i4
    int o  = id >> 8;
    int i4 = id & 255;
    size_t fo = (size_t)o * 256 + i4;
    float4 w0 = ((const float4*)W0)[fo];
    float4 w1 = ((const float4*)W1)[fo];
    float4 w2 = ((const float4*)W2)[fo];
    float4 w3 = ((const float4*)W3)[fo];

    __half2* R = (__half2*)g_wh8;
    size_t stride2 = (size_t)1024 * 512;
    size_t base = (size_t)o * 512 + i4 * 2;

    float4 vals[8];
    vals[0] = w0; vals[1] = w1; vals[2] = w2; vals[3] = w3;
    vals[4] = make_float4(w0.x + w1.x, w0.y + w1.y, w0.z + w1.z, w0.w + w1.w);
    vals[5] = make_float4(w2.x - w3.x, w2.y - w3.y, w2.z - w3.z, w2.w - w3.w);
    vals[6] = make_float4(w2.x + w3.x, w2.y + w3.y, w2.z + w3.z, w2.w + w3.w);
    vals[7] = make_float4(w0.x - w1.x, w0.y - w1.y, w0.z - w1.z, w0.w - w1.w);
#pragma unroll
    for (int r = 0; r < 8; r++) {
        R[r * stride2 + base]     = make_half2(__float2half_rn(vals[r].x),
                                               __float2half_rn(vals[r].y));
        R[r * stride2 + base + 1] = make_half2(__float2half_rn(vals[r].z),
                                               __float2half_rn(vals[r].w));
    }
}

__global__ void k_bias(const float* __restrict__ b0, const float* __restrict__ b1,
                       const float* __restrict__ b2, const float* __restrict__ b3) {
    int n = blockIdx.x * blockDim.x + threadIdx.x;
    if (n >= OUT_F) return;
    int co = n >> 10, o = n & 1023;
    const float* B[4] = {b0, b1, b2, b3};
    float acc = 0.f;
#pragma unroll
    for (int ci = 0; ci < 4; ci++) acc += c_s[co][ci] * B[c_q[co][ci]][o];
    g_bias[n] = acc;
}

// ------------------------------- GEMM kernel --------------------------------

__device__ __forceinline__ void load_stage(uint32_t sb, int slot, int it,
                                           int pair, int m0, int n0, int tid) {
    const int t   = it >> 4;                 // segment 0..5
    const int kts = it & 15;                 // kt within segment
    const __half* aG = g_lh  + (size_t)c_lidx[t] * (BATCH * 1024)
                             + (size_t)m0 * 1024 + kts * BK;
    const __half* bG = g_wh8 + (size_t)c_ridx[pair][t] * (1024 * 1024)
                             + (size_t)n0 * 1024 + kts * BK;
    const uint32_t st = sb + slot * STAGE_BYTES;
    // A: 128 rows x 8 chunks of 16B = 1024 chunks; 2 per thread (512 thr)
#pragma unroll
    for (int j = 0; j < 2; j++) {
        int c   = tid + j * THREADS;
        int row = c >> 3;
        int ko  = c & 7;
        cp16(st + row * ROWB + ko * 16, aG + (size_t)row * 1024 + ko * 8);
    }
    // B: 128 rows x 8 chunks; 2 per thread
#pragma unroll
    for (int j = 0; j < 2; j++) {
        int c   = tid + j * THREADS;
        int row = c >> 3;
        int ko  = c & 7;
        cp16(st + A_ST_BYTES + row * ROWB + ko * 16,
             bG + (size_t)row * 1024 + ko * 8);
    }
}

__global__ void __launch_bounds__(THREADS, 1) k_gemm(float* __restrict__ out) {
    extern __shared__ char smem[];
    const uint32_t sb = smem_u32(smem);
    const int tid = threadIdx.x;
    const int wid = tid >> 5;
    const int lid = tid & 31;
    const int pair = blockIdx.z;           // 0 -> (r,i), 1 -> (j,k)
    const int m0 = blockIdx.y * BM;
    const int n0 = blockIdx.x * BN;        // within 0..1023

    const int wm = wid & 3;                // 4 m-warps (32 rows each)
    const int wn = wid >> 2;               // 4 n-warps (32 cols each)
    const int gid = lid >> 2;
    const int tig = lid & 3;

    // ldmatrix per-lane base addresses (stage 0)
    const uint32_t aL0 = sb
        + (uint32_t)(wm * 32 + (lid & 15)) * ROWB + (uint32_t)(lid >> 4) * 16;
    const uint32_t bL0 = sb + A_ST_BYTES
        + (uint32_t)(wn * 32 + ((lid >> 4) * 8) + (lid & 7)) * ROWB
        + (uint32_t)((lid >> 3) & 1) * 16;

    // warp tile 32x32: 2 m-frags x 4 n-frags; 3 accumulator sets = 96 fp32
    float accP[2][4][4], accA[2][4][4], accB[2][4][4];
#pragma unroll
    for (int mf = 0; mf < 2; mf++)
#pragma unroll
        for (int nf = 0; nf < 4; nf++)
#pragma unroll
            for (int r = 0; r < 4; r++) {
                accP[mf][nf][r] = 0.f; accA[mf][nf][r] = 0.f; accB[mf][nf][r] = 0.f;
            }

    // prologue
    load_stage(sb, 0, 0, pair, m0, n0, tid); cp_commit();
    load_stage(sb, 1, 1, pair, m0, n0, tid); cp_commit();

    int slot = 0;
    for (int it = 0; it < TOT_KT; it++) {
        cp_wait<1>();
        __syncthreads();

        if (it + 2 < TOT_KT) {
            int ns = slot + 2; if (ns >= STAGES) ns -= STAGES;
            load_stage(sb, ns, it + 2, pair, m0, n0, tid);
        }
        cp_commit();

        const uint32_t aS = aL0 + slot * STAGE_BYTES;
        const uint32_t bS = bL0 + slot * STAGE_BYTES;

#pragma unroll
        for (int kk = 0; kk < 4; kk++) {
            uint32_t a[2][4];
            ldmx4(a[0], aS + kk * 32);
            ldmx4(a[1], aS + 16 * ROWB + kk * 32);
#pragma unroll
            for (int np = 0; np < 2; np++) {           // 2 n-pairs (32 cols)
                uint32_t bq[4];
                ldmx4(bq, bS + np * (16 * ROWB) + kk * 32);
                mma_f16(accP[0][2 * np],     a[0], bq[0], bq[1]);
                mma_f16(accP[1][2 * np],     a[1], bq[0], bq[1]);
                mma_f16(accP[0][2 * np + 1], a[0], bq[2], bq[3]);
                mma_f16(accP[1][2 * np + 1], a[1], bq[2], bq[3]);
            }
        }

        // segment boundary: fold product accumulator into the two outputs
        if ((it & 15) == 15) {
            const int t = it >> 4;
            const float sA = c_sA[pair][t];
            const float sB = c_sB[pair][t];
#pragma unroll
            for (int mf = 0; mf < 2; mf++)
#pragma unroll
                for (int nf = 0; nf < 4; nf++)
#pragma unroll
                    for (int r = 0; r < 4; r++) {
                        accA[mf][nf][r] += sA * accP[mf][nf][r];
                        accB[mf][nf][r] += sB * accP[mf][nf][r];
                        accP[mf][nf][r] = 0.f;
                    }
        }

        slot++; if (slot >= STAGES) slot = 0;
    }

    // ---- epilogue: two components ----
    const int compA = 2 * pair;       // r or j
    const int compB = 2 * pair + 1;   // i or k
    float2 bvA[4], bvB[4];
#pragma unroll
    for (int nf = 0; nf < 4; nf++) {
        int c = n0 + wn * 32 + nf * 8 + tig * 2;
        bvA[nf] = make_float2(g_bias[compA * 1024 + c], g_bias[compA * 1024 + c + 1]);
        bvB[nf] = make_float2(g_bias[compB * 1024 + c], g_bias[compB * 1024 + c + 1]);
    }
#pragma unroll
    for (int mf = 0; mf < 2; mf++) {
        int r0 = m0 + wm * 32 + mf * 16 + gid;
#pragma unroll
        for (int nf = 0; nf < 4; nf++) {
            int c = n0 + wn * 32 + nf * 8 + tig * 2;
            float* oA0 = out + (size_t)r0 * OUT_F + compA * 1024 + c;
            float* oB0 = out + (size_t)r0 * OUT_F + compB * 1024 + c;
            *(float2*)oA0 = make_float2(accA[mf][nf][0] + bvA[nf].x,
                                        accA[mf][nf][1] + bvA[nf].y);
            *(float2*)(oA0 + 8 * OUT_F) = make_float2(accA[mf][nf][2] + bvA[nf].x,
                                                      accA[mf][nf][3] + bvA[nf].y);
            *(float2*)oB0 = make_float2(accB[mf][nf][0] + bvB[nf].x,
                                        accB[mf][nf][1] + bvB[nf].y);
            *(float2*)(oB0 + 8 * OUT_F) = make_float2(accB[mf][nf][2] + bvB[nf].x,
                                                      accB[mf][nf][3] + bvB[nf].y);
        }
    }
}

// ------------------------------- launcher -----------------------------------

extern "C" void kernel_launch(void* const* d_in, const int* in_sizes, int n_in,
                              void* d_out, int out_size) {
    // Identify inputs by element count (robust to metadata ordering):
    //   x: 16777216;  W_*: 1048576 each;  b_*: 1024 each (OUT_Q)
    const float* x = nullptr;
    const float* W[4] = {nullptr, nullptr, nullptr, nullptr};
    const float* b[4] = {nullptr, nullptr, nullptr, nullptr};
    int wn = 0, bn = 0;
    for (int i = 0; i < n_in; i++) {
        if (in_sizes[i] == BATCH * IN_F)    x = (const float*)d_in[i];
        else if (in_sizes[i] == W_ELEMS)    { if (wn < 4) W[wn++] = (const float*)d_in[i]; }
        else if (in_sizes[i] == QOUT)       { if (bn < 4) b[bn++] = (const float*)d_in[i]; }
    }
    if (!x || wn != 4 || bn != 4) return;

    cudaFuncSetAttribute(k_gemm, cudaFuncAttributeMaxDynamicSharedMemorySize,
                         SMEM_TOTAL);

    k_lhs<<<(BATCH * 256) / 256, 256>>>(x);
    k_rhs<<<(1024 * 256) / 256, 256>>>(W[0], W[1], W[2], W[3]);
    k_bias<<<OUT_F / 256, 256>>>(b[0], b[1], b[2], b[3]);

    dim3 grid(1024 / BN, BATCH / BM, 2);
    k_gemm<<<grid, THREADS, SMEM_TOTAL>>>((float*)d_out);
}

// round 16
// speedup vs baseline: 1.1224x; 1.1224x over previous
#include <cuda_runtime.h>
#include <cuda_fp16.h>
#include <cstdint>
#include <cstddef>

// ---------------------------------------------------------------------------
// QDense via quaternion complex-Karatsuba: 12 products of [B,1024]x[1024,1024]
// (75% of dense MACs; tensor-busy measured invariant at 169us = 0.75 x 225us).
// R15->R16: revert to R14 config (warp tile 32x64, 256 thr, 3 acc sets) and
//   halve pipeline iterations with BK=128 (256B rows, pad 272B) to cut the
//   per-kt barrier/wait residual (~220cyc x 332kt/SM ~= 40us).
//   P1=x0W0 P2=x1W1 P3=(x0+x1)(W0+W1)  P4=x2W2 P5=x3W3 P6=(x2+x3)(W2-W3)
//   P7=x0W2 P8=x1W3 P9=(x0+x1)(W2+W3)  P10=x2W0 P11=x3W1 P12=(x2+x3)(W0-W1)
//   out_r=P1-P2-P4-P5            out_i=-P1-P2+P3+P4-P5-P6
//   out_j=P7-P8+P10+P11          out_k=-P7-P8+P9-P10+P11+P12
// ---------------------------------------------------------------------------

#define IN_F   4096
#define OUT_F  4096
#define BATCH  4096
#define QOUT   1024
#define W_ELEMS (1024 * 1024)

#define BM 128
#define BN 128
#define BK 128                         // k half-elements per stage (256B rows)
#define STAGES 3
#define SEGS 6
#define KT_PER_SEG 8                   // 1024 / 128
#define TOT_KT (SEGS * KT_PER_SEG)     // 48
#define THREADS 256

#define ROWB 272                       // padded row stride in bytes (256+16)
#define A_ST_BYTES (BM * ROWB)         // 34816
#define B_ST_BYTES (BN * ROWB)         // 34816
#define STAGE_BYTES (A_ST_BYTES + B_ST_BYTES)   // 69632
#define SMEM_TOTAL (STAGES * STAGE_BYTES)       // 208896

// Scratch: device globals (the only legal scratch)
__device__ __half g_lh[(size_t)6 * BATCH * 1024];   // L0..L5          (48 MB)
__device__ __half g_wh8[(size_t)8 * 1024 * 1024];   // 8 RHS matrices  (16 MB)
__device__ float  g_bias[OUT_F];

__constant__ int   c_q[4][4] = {{0,1,2,3},{1,0,3,2},{2,3,0,1},{3,2,1,0}};
__constant__ float c_s[4][4] = {{ 1.f,-1.f,-1.f,-1.f},
                                { 1.f, 1.f, 1.f,-1.f},
                                { 1.f,-1.f, 1.f, 1.f},
                                { 1.f, 1.f,-1.f, 1.f}};

// per-segment LHS index, RHS index per pair, fold signs per pair
__constant__ int   c_lidx[6]    = {0, 1, 4, 2, 3, 5};
__constant__ int   c_ridx[2][6] = {{0, 1, 4, 2, 3, 5},   // W0 W1 W0+W1 W2 W3 W2-W3
                                   {2, 3, 6, 0, 1, 7}};  // W2 W3 W2+W3 W0 W1 W0-W1
__constant__ float c_sA[2][6] = {{ 1.f,-1.f, 0.f,-1.f,-1.f, 0.f},   // out_r / out_j
                                 { 1.f,-1.f, 0.f, 1.f, 1.f, 0.f}};
__constant__ float c_sB[2][6] = {{-1.f,-1.f, 1.f, 1.f,-1.f,-1.f},   // out_i / out_k
                                 {-1.f,-1.f, 1.f,-1.f, 1.f, 1.f}};

// ------------------------------- helpers -----------------------------------

__device__ __forceinline__ uint32_t smem_u32(const void* p) {
    uint32_t a;
    asm("{ .reg .u64 t; cvta.to.shared.u64 t, %1; cvt.u32.u64 %0, t; }"
        : "=r"(a) : "l"(p));
    return a;
}

__device__ __forceinline__ void cp16(uint32_t dst, const void* src) {
    asm volatile("cp.async.cg.shared.global [%0], [%1], 16;" :: "r"(dst), "l"(src));
}

__device__ __forceinline__ void cp_commit() {
    asm volatile("cp.async.commit_group;" ::: "memory");
}

template <int N>
__device__ __forceinline__ void cp_wait() {
    asm volatile("cp.async.wait_group %0;" :: "n"(N) : "memory");
}

__device__ __forceinline__ void ldmx4(uint32_t* r, uint32_t addr) {
    asm volatile(
        "ldmatrix.sync.aligned.m8n8.x4.shared.b16 {%0,%1,%2,%3}, [%4];"
        : "=r"(r[0]), "=r"(r[1]), "=r"(r[2]), "=r"(r[3]) : "r"(addr));
}

__device__ __forceinline__ void mma_f16(float* d, const uint32_t* a,
                                        uint32_t b0, uint32_t b1) {
    asm volatile(
        "mma.sync.aligned.m16n8k16.row.col.f32.f16.f16.f32 "
        "{%0,%1,%2,%3}, {%4,%5,%6,%7}, {%8,%9}, {%0,%1,%2,%3};"
        : "+f"(d[0]), "+f"(d[1]), "+f"(d[2]), "+f"(d[3])
        : "r"(a[0]), "r"(a[1]), "r"(a[2]), "r"(a[3]), "r"(b0), "r"(b1));
}

// ------------------------------ prep kernels --------------------------------

// Build L0..L3 (x components) and L4=x0+x1, L5=x2+x3, all fp16.
__global__ void k_lhs(const float* __restrict__ x) {
    int id = blockIdx.x * blockDim.x + threadIdx.x;     // b*256 + i4
    int b  = id >> 8;
    int i4 = id & 255;                                  // float4 within 1024
    const float4* xr = (const float4*)x + (size_t)b * 1024;  // 1024 float4/row
    float4 v[4];
#pragma unroll
    for (int c = 0; c < 4; c++) v[c] = xr[c * 256 + i4];

    __half2* L = (__half2*)g_lh;
    size_t stride2 = (size_t)BATCH * 512;               // half2 per L matrix
    size_t base = (size_t)b * 512 + i4 * 2;             // half2 idx within matrix
#pragma unroll
    for (int c = 0; c < 4; c++) {
        L[c * stride2 + base]     = make_half2(__float2half_rn(v[c].x),
                                               __float2half_rn(v[c].y));
        L[c * stride2 + base + 1] = make_half2(__float2half_rn(v[c].z),
                                               __float2half_rn(v[c].w));
    }
    float4 s01 = make_float4(v[0].x + v[1].x, v[0].y + v[1].y,
                             v[0].z + v[1].z, v[0].w + v[1].w);
    float4 s23 = make_float4(v[2].x + v[3].x, v[2].y + v[3].y,
                             v[2].z + v[3].z, v[2].w + v[3].w);
    L[4 * stride2 + base]     = make_half2(__float2half_rn(s01.x), __float2half_rn(s01.y));
    L[4 * stride2 + base + 1] = make_half2(__float2half_rn(s01.z), __float2half_rn(s01.w));
    L[5 * stride2 + base]     = make_half2(__float2half_rn(s23.x), __float2half_rn(s23.y));
    L[5 * stride2 + base + 1] = make_half2(__float2half_rn(s23.z), __float2half_rn(s23.w));
}

// Build 8 RHS matrices: 0..3 = W0..W3, 4=W0+W1, 5=W2-W3, 6=W2+W3, 7=W0-W1.
__global__ void k_rhs(const float* __restrict__ W0, const float* __restrict__ W1,
                      const float* __restrict__ W2, const float* __restrict__ W3) {
    int id = blockIdx.x * blockDim.x + threadIdx.x;     // o*256 + i4
    int o  = id >> 8;
    int i4 = id & 255;
    size_t fo = (size_t)o * 256 + i4;
    float4 w0 = ((const float4*)W0)[fo];
    float4 w1 = ((const float4*)W1)[fo];
    float4 w2 = ((const float4*)W2)[fo];
    float4 w3 = ((const float4*)W3)[fo];

    __half2* R = (__half2*)g_wh8;
    size_t stride2 = (size_t)1024 * 512;
    size_t base = (size_t)o * 512 + i4 * 2;

    float4 vals[8];
    vals[0] = w0; vals[1] = w1; vals[2] = w2; vals[3] = w3;
    vals[4] = make_float4(w0.x + w1.x, w0.y + w1.y, w0.z + w1.z, w0.w + w1.w);
    vals[5] = make_float4(w2.x - w3.x, w2.y - w3.y, w2.z - w3.z, w2.w - w3.w);
    vals[6] = make_float4(w2.x + w3.x, w2.y + w3.y, w2.z + w3.z, w2.w + w3.w);
    vals[7] = make_float4(w0.x - w1.x, w0.y - w1.y, w0.z - w1.z, w0.w - w1.w);
#pragma unroll
    for (int r = 0; r < 8; r++) {
        R[r * stride2 + base]     = make_half2(__float2half_rn(vals[r].x),
                                               __float2half_rn(vals[r].y));
        R[r * stride2 + base + 1] = make_half2(__float2half_rn(vals[r].z),
                                               __float2half_rn(vals[r].w));
    }
}

__global__ void k_bias(const float* __restrict__ b0, const float* __restrict__ b1,
                       const float* __restrict__ b2, const float* __restrict__ b3) {
    int n = blockIdx.x * blockDim.x + threadIdx.x;
    if (n >= OUT_F) return;
    int co = n >> 10, o = n & 1023;
    const float* B[4] = {b0, b1, b2, b3};
    float acc = 0.f;
#pragma unroll
    for (int ci = 0; ci < 4; ci++) acc += c_s[co][ci] * B[c_q[co][ci]][o];
    g_bias[n] = acc;
}

// ------------------------------- GEMM kernel --------------------------------

__device__ __forceinline__ void load_stage(uint32_t sb, int slot, int it,
                                           int pair, int m0, int n0, int tid) {
    const int t   = it >> 3;                 // segment 0..5
    const int kts = it & 7;                  // kt within segment
    const __half* aG = g_lh  + (size_t)c_lidx[t] * (BATCH * 1024)
                             + (size_t)m0 * 1024 + kts * BK;
    const __half* bG = g_wh8 + (size_t)c_ridx[pair][t] * (1024 * 1024)
                             + (size_t)n0 * 1024 + kts * BK;
    const uint32_t st = sb + slot * STAGE_BYTES;
    // A: 128 rows x 16 chunks of 16B = 2048 chunks; 8 per thread (256 thr)
#pragma unroll
    for (int j = 0; j < 8; j++) {
        int c   = tid + j * THREADS;
        int row = c >> 4;
        int ko  = c & 15;
        cp16(st + row * ROWB + ko * 16, aG + (size_t)row * 1024 + ko * 8);
    }
    // B: 128 rows x 16 chunks; 8 per thread
#pragma unroll
    for (int j = 0; j < 8; j++) {
        int c   = tid + j * THREADS;
        int row = c >> 4;
        int ko  = c & 15;
        cp16(st + A_ST_BYTES + row * ROWB + ko * 16,
             bG + (size_t)row * 1024 + ko * 8);
    }
}

__global__ void __launch_bounds__(THREADS, 1) k_gemm(float* __restrict__ out) {
    extern __shared__ char smem[];
    const uint32_t sb = smem_u32(smem);
    const int tid = threadIdx.x;
    const int wid = tid >> 5;
    const int lid = tid & 31;
    const int pair = blockIdx.z;           // 0 -> (r,i), 1 -> (j,k)
    const int m0 = blockIdx.y * BM;
    const int n0 = blockIdx.x * BN;        // within 0..1023

    const int wm = wid & 3;                // 4 m-warps (32 rows each)
    const int wn = wid >> 2;               // 2 n-warps (64 cols each)
    const int gid = lid >> 2;
    const int tig = lid & 3;

    // ldmatrix per-lane base addresses (stage 0)
    const uint32_t aL0 = sb
        + (uint32_t)(wm * 32 + (lid & 15)) * ROWB + (uint32_t)(lid >> 4) * 16;
    const uint32_t bL0 = sb + A_ST_BYTES
        + (uint32_t)(wn * 64 + ((lid >> 4) * 8) + (lid & 7)) * ROWB
        + (uint32_t)((lid >> 3) & 1) * 16;

    // warp tile 32x64: 2 m-frags x 8 n-frags; 3 accumulator sets
    float accP[2][8][4], accA[2][8][4], accB[2][8][4];
#pragma unroll
    for (int mf = 0; mf < 2; mf++)
#pragma unroll
        for (int nf = 0; nf < 8; nf++)
#pragma unroll
            for (int r = 0; r < 4; r++) {
                accP[mf][nf][r] = 0.f; accA[mf][nf][r] = 0.f; accB[mf][nf][r] = 0.f;
            }

    // prologue
    load_stage(sb, 0, 0, pair, m0, n0, tid); cp_commit();
    load_stage(sb, 1, 1, pair, m0, n0, tid); cp_commit();

    int slot = 0;
    for (int it = 0; it < TOT_KT; it++) {
        cp_wait<1>();
        __syncthreads();

        if (it + 2 < TOT_KT) {
            int ns = slot + 2; if (ns >= STAGES) ns -= STAGES;
            load_stage(sb, ns, it + 2, pair, m0, n0, tid);
        }
        cp_commit();

        const uint32_t aS = aL0 + slot * STAGE_BYTES;
        const uint32_t bS = bL0 + slot * STAGE_BYTES;

        // 8 x k16 chunks per stage (BK=128)
#pragma unroll
        for (int kk = 0; kk < 8; kk++) {
            uint32_t a[2][4];
            ldmx4(a[0], aS + kk * 32);
            ldmx4(a[1], aS + 16 * ROWB + kk * 32);
#pragma unroll
            for (int np = 0; np < 4; np++) {           // 4 n-pairs (64 cols)
                uint32_t bq[4];
                ldmx4(bq, bS + np * (16 * ROWB) + kk * 32);
                mma_f16(accP[0][2 * np],     a[0], bq[0], bq[1]);
                mma_f16(accP[1][2 * np],     a[1], bq[0], bq[1]);
                mma_f16(accP[0][2 * np + 1], a[0], bq[2], bq[3]);
                mma_f16(accP[1][2 * np + 1], a[1], bq[2], bq[3]);
            }
        }

        // segment boundary: fold product accumulator into the two outputs
        if ((it & 7) == 7) {
            const int t = it >> 3;
            const float sA = c_sA[pair][t];
            const float sB = c_sB[pair][t];
#pragma unroll
            for (int mf = 0; mf < 2; mf++)
#pragma unroll
                for (int nf = 0; nf < 8; nf++)
#pragma unroll
                    for (int r = 0; r < 4; r++) {
                        accA[mf][nf][r] += sA * accP[mf][nf][r];
                        accB[mf][nf][r] += sB * accP[mf][nf][r];
                        accP[mf][nf][r] = 0.f;
                    }
        }

        slot++; if (slot >= STAGES) slot = 0;
    }

    // ---- epilogue: two components ----
    const int compA = 2 * pair;       // r or j
    const int compB = 2 * pair + 1;   // i or k
    float2 bvA[8], bvB[8];
#pragma unroll
    for (int nf = 0; nf < 8; nf++) {
        int c = n0 + wn * 64 + nf * 8 + tig * 2;
        bvA[nf] = make_float2(g_bias[compA * 1024 + c], g_bias[compA * 1024 + c + 1]);
        bvB[nf] = make_float2(g_bias[compB * 1024 + c], g_bias[compB * 1024 + c + 1]);
    }
#pragma unroll
    for (int mf = 0; mf < 2; mf++) {
        int r0 = m0 + wm * 32 + mf * 16 + gid;
#pragma unroll
        for (int nf = 0; nf < 8; nf++) {
            int c = n0 + wn * 64 + nf * 8 + tig * 2;
            float* oA0 = out + (size_t)r0 * OUT_F + compA * 1024 + c;
            float* oB0 = out + (size_t)r0 * OUT_F + compB * 1024 + c;
            *(float2*)oA0 = make_float2(accA[mf][nf][0] + bvA[nf].x,
                                        accA[mf][nf][1] + bvA[nf].y);
            *(float2*)(oA0 + 8 * OUT_F) = make_float2(accA[mf][nf][2] + bvA[nf].x,
                                                      accA[mf][nf][3] + bvA[nf].y);
            *(float2*)oB0 = make_float2(accB[mf][nf][0] + bvB[nf].x,
                                        accB[mf][nf][1] + bvB[nf].y);
            *(float2*)(oB0 + 8 * OUT_F) = make_float2(accB[mf][nf][2] + bvB[nf].x,
                                                      accB[mf][nf][3] + bvB[nf].y);
        }
    }
}

// ------------------------------- launcher -----------------------------------

extern "C" void kernel_launch(void* const* d_in, const int* in_sizes, int n_in,
                              void* d_out, int out_size) {
    // Identify inputs by element count (robust to metadata ordering):
    //   x: 16777216;  W_*: 1048576 each;  b_*: 1024 each (OUT_Q)
    const float* x = nullptr;
    const float* W[4] = {nullptr, nullptr, nullptr, nullptr};
    const float* b[4] = {nullptr, nullptr, nullptr, nullptr};
    int wn = 0, bn = 0;
    for (int i = 0; i < n_in; i++) {
        if (in_sizes[i] == BATCH * IN_F)    x = (const float*)d_in[i];
        else if (in_sizes[i] == W_ELEMS)    { if (wn < 4) W[wn++] = (const float*)d_in[i]; }
        else if (in_sizes[i] == QOUT)       { if (bn < 4) b[bn++] = (const float*)d_in[i]; }
    }
    if (!x || wn != 4 || bn != 4) return;

    cudaFuncSetAttribute(k_gemm, cudaFuncAttributeMaxDynamicSharedMemorySize,
                         SMEM_TOTAL);

    k_lhs<<<(BATCH * 256) / 256, 256>>>(x);
    k_rhs<<<(1024 * 256) / 256, 256>>>(W[0], W[1], W[2], W[3]);
    k_bias<<<OUT_F / 256, 256>>>(b[0], b[1], b[2], b[3]);

    dim3 grid(1024 / BN, BATCH / BM, 2);
    k_gemm<<<grid, THREADS, SMEM_TOTAL>>>((float*)d_out);
}